// round 2
// baseline (speedup 1.0000x reference)
#include <cuda_runtime.h>
#include <math.h>
#include <stdint.h>

#define OLDV 50257
#define NEWV 53257
#define EMB_D 2048
#define T_TOK 32768
#define NNUM 4096
#define KDIM 8192           // 4*D
#define MGEMM 4096
#define NGEMM 2048

// 128 MB scratch for the hidden activations h = gelu(feats@W1 + b1)
__device__ float g_h[(size_t)NNUM * KDIM];

// ---------------------------------------------------------------------------
// Kernel 1: embedding gather/select. One block per token, copy 2048 floats.
// ---------------------------------------------------------------------------
__global__ void gather_kernel(const int* __restrict__ ids,
                              const float* __restrict__ orig_emb,
                              const float* __restrict__ new_emb,
                              float* __restrict__ out) {
    int t = blockIdx.x;
    int id = ids[t];
    const float4* src = (id >= OLDV)
        ? (const float4*)(new_emb + (size_t)(id - OLDV) * EMB_D)
        : (const float4*)(orig_emb + (size_t)id * EMB_D);
    float4* dst = (float4*)(out + (size_t)t * EMB_D);
    int i = threadIdx.x;
    dst[i]       = src[i];
    dst[i + 256] = src[i + 256];
}

// ---------------------------------------------------------------------------
// Kernel 2: h[i,k] = gelu_exact(v_i*W1[0,k] + e0_i*W1[1,k] + e1_i*W1[2,k] + b1[k])
// ---------------------------------------------------------------------------
__device__ __forceinline__ float gelu_exact(float x) {
    return 0.5f * x * (1.0f + erff(x * 0.70710678118654752440f));
}

__global__ void hidden_kernel(const float* __restrict__ vals,
                              const int* __restrict__ units,
                              const float* __restrict__ unit_emb,
                              const float* __restrict__ W1,
                              const float* __restrict__ b1) {
    int i = blockIdx.y;
    float v = vals[i];
    int u = units[i];
    float e0 = unit_emb[u * 2];
    float e1 = unit_emb[u * 2 + 1];
    int k = (blockIdx.x * blockDim.x + threadIdx.x) * 4;
    float4 w0 = *(const float4*)&W1[k];
    float4 w1 = *(const float4*)&W1[KDIM + k];
    float4 w2 = *(const float4*)&W1[2 * KDIM + k];
    float4 bb = *(const float4*)&b1[k];
    float4 r;
    r.x = gelu_exact(fmaf(v, w0.x, fmaf(e0, w1.x, fmaf(e1, w2.x, bb.x))));
    r.y = gelu_exact(fmaf(v, w0.y, fmaf(e0, w1.y, fmaf(e1, w2.y, bb.y))));
    r.z = gelu_exact(fmaf(v, w0.z, fmaf(e0, w1.z, fmaf(e1, w2.z, bb.z))));
    r.w = gelu_exact(fmaf(v, w0.w, fmaf(e0, w1.w, fmaf(e1, w2.w, bb.w))));
    *(float4*)&g_h[(size_t)i * KDIM + k] = r;
}

// ---------------------------------------------------------------------------
// Kernel 3: out[pos[m], n0+n] += (h @ W2)[m, n] + b2[n]
// 128x128x16 tiles, 256 threads, 8x8 microtile per thread, packed f32x2 FMA.
// ---------------------------------------------------------------------------
#define BM 128
#define BN 128
#define BK 16

__global__ __launch_bounds__(256, 2)
void gemm_add_kernel(const float* __restrict__ W2,
                     const float* __restrict__ b2,
                     const int* __restrict__ pos,
                     float* __restrict__ out) {
    __shared__ __align__(16) float As[2][BK][BM + 4];
    __shared__ __align__(16) float Bs[2][BK][BN];

    const float* A = g_h;
    const int m0 = blockIdx.y * BM;
    const int n0 = blockIdx.x * BN;
    const int tid = threadIdx.x;
    const int tx = tid & 15;
    const int ty = tid >> 4;

    // global->shared load mapping
    const int ar = tid >> 2;          // 0..63
    const int ac = (tid & 3) * 4;     // 0,4,8,12
    const int br = tid >> 5;          // 0..7
    const int bc = (tid & 31) * 4;    // 0..124

    const float* Aptr = A + (size_t)m0 * KDIM;

    // prologue: tile 0
    #pragma unroll
    for (int l = 0; l < 2; l++) {
        int r = ar + l * 64;
        float4 v = *(const float4*)&Aptr[(size_t)r * KDIM + ac];
        As[0][ac + 0][r] = v.x; As[0][ac + 1][r] = v.y;
        As[0][ac + 2][r] = v.z; As[0][ac + 3][r] = v.w;
    }
    #pragma unroll
    for (int l = 0; l < 2; l++) {
        int r = br + l * 8;
        float4 v = *(const float4*)&W2[(size_t)r * NGEMM + n0 + bc];
        *(float4*)&Bs[0][r][bc] = v;
    }
    __syncthreads();

    unsigned long long acc[8][4];
    #pragma unroll
    for (int i = 0; i < 8; i++)
        #pragma unroll
        for (int j = 0; j < 4; j++) acc[i][j] = 0ull;

    const int NKT = KDIM / BK;  // 512
    for (int kt = 0; kt < NKT; kt++) {
        const int p = kt & 1;
        float4 atile[2], btile[2];
        if (kt + 1 < NKT) {
            const int kbase = (kt + 1) * BK;
            #pragma unroll
            for (int l = 0; l < 2; l++) {
                int r = ar + l * 64;
                atile[l] = *(const float4*)&Aptr[(size_t)r * KDIM + kbase + ac];
            }
            #pragma unroll
            for (int l = 0; l < 2; l++) {
                int r = br + l * 8;
                btile[l] = *(const float4*)&W2[(size_t)(kbase + r) * NGEMM + n0 + bc];
            }
        }
        #pragma unroll
        for (int k = 0; k < BK; k++) {
            float a[8];
            *(float4*)&a[0] = *(const float4*)&As[p][k][ty * 8];
            *(float4*)&a[4] = *(const float4*)&As[p][k][ty * 8 + 4];
            unsigned long long bv[4];
            {
                ulonglong2 bb0 = *(const ulonglong2*)&Bs[p][k][tx * 8];
                ulonglong2 bb1 = *(const ulonglong2*)&Bs[p][k][tx * 8 + 4];
                bv[0] = bb0.x; bv[1] = bb0.y; bv[2] = bb1.x; bv[3] = bb1.y;
            }
            #pragma unroll
            for (int i = 0; i < 8; i++) {
                unsigned long long av;
                unsigned int ai = __float_as_uint(a[i]);
                asm("mov.b64 %0, {%1, %1};" : "=l"(av) : "r"(ai));
                #pragma unroll
                for (int j = 0; j < 4; j++) {
                    asm("fma.rn.f32x2 %0, %1, %2, %3;"
                        : "=l"(acc[i][j])
                        : "l"(av), "l"(bv[j]), "l"(acc[i][j]));
                }
            }
        }
        if (kt + 1 < NKT) {
            const int q = p ^ 1;
            #pragma unroll
            for (int l = 0; l < 2; l++) {
                int r = ar + l * 64;
                As[q][ac + 0][r] = atile[l].x; As[q][ac + 1][r] = atile[l].y;
                As[q][ac + 2][r] = atile[l].z; As[q][ac + 3][r] = atile[l].w;
            }
            #pragma unroll
            for (int l = 0; l < 2; l++) {
                int r = br + l * 8;
                *(float4*)&Bs[q][r][bc] = btile[l];
            }
        }
        __syncthreads();
    }

    // epilogue: scatter-add into out rows given by num_positions
    #pragma unroll
    for (int i = 0; i < 8; i++) {
        int m = m0 + ty * 8 + i;
        int prow = pos[m];
        float* op = out + (size_t)prow * EMB_D + n0 + tx * 8;
        const float* bp = b2 + n0 + tx * 8;
        #pragma unroll
        for (int j = 0; j < 4; j++) {
            unsigned int lo = (unsigned int)(acc[i][j] & 0xFFFFFFFFull);
            unsigned int hi = (unsigned int)(acc[i][j] >> 32);
            float2 cur = *(float2*)&op[j * 2];
            cur.x += __uint_as_float(lo) + bp[j * 2];
            cur.y += __uint_as_float(hi) + bp[j * 2 + 1];
            *(float2*)&op[j * 2] = cur;
        }
    }
}

// ---------------------------------------------------------------------------
extern "C" void kernel_launch(void* const* d_in, const int* in_sizes, int n_in,
                              void* d_out, int out_size) {
    const int*   input_ids  = (const int*)d_in[0];
    const int*   num_pos    = (const int*)d_in[1];
    const float* num_values = (const float*)d_in[2];
    const int*   num_units  = (const int*)d_in[3];
    const float* orig_emb   = (const float*)d_in[4];
    const float* new_emb    = (const float*)d_in[5];
    const float* unit_emb   = (const float*)d_in[6];
    const float* W1         = (const float*)d_in[7];
    const float* b1         = (const float*)d_in[8];
    const float* W2         = (const float*)d_in[9];
    const float* b2         = (const float*)d_in[10];
    float* out = (float*)d_out;

    // 1) gather/select embeddings for all tokens
    gather_kernel<<<T_TOK, 256>>>(input_ids, orig_emb, new_emb, out);

    // 2) hidden activations h = gelu(feats @ W1 + b1)
    dim3 hgrid(KDIM / (256 * 4), NNUM);
    hidden_kernel<<<hgrid, 256>>>(num_values, num_units, unit_emb, W1, b1);

    // 3) GEMM + scatter-add epilogue
    dim3 ggrid(NGEMM / BN, MGEMM / BM);
    gemm_add_kernel<<<ggrid, 256>>>(W2, b2, num_pos, out);
}

// round 5
// speedup vs baseline: 5.4688x; 5.4688x over previous
#include <cuda_runtime.h>
#include <cuda_fp16.h>
#include <math.h>
#include <stdint.h>

#define OLDV 50257
#define EMB_D 2048
#define T_TOK 32768
#define NNUM 4096
#define KDIM 8192
#define MGEMM 4096
#define NGEMM 2048

// fp16 scratch: hidden activations and W2
__device__ __align__(128) __half g_hh[(size_t)NNUM * KDIM];    // [4096, 8192] row-major
__device__ __align__(128) __half g_w2h[(size_t)KDIM * NGEMM];  // [8192, 2048] row-major

// ---------------------------------------------------------------------------
// helpers
// ---------------------------------------------------------------------------
__device__ __forceinline__ uint32_t s2u(const void* p) {
    uint32_t a;
    asm("{ .reg .u64 t; cvta.to.shared.u64 t, %1; cvt.u32.u64 %0, t; }"
        : "=r"(a) : "l"(p));
    return a;
}
__device__ __forceinline__ void ldsm_x4(uint32_t* r, uint32_t addr) {
    asm volatile("ldmatrix.sync.aligned.m8n8.x4.shared.b16 {%0,%1,%2,%3}, [%4];"
                 : "=r"(r[0]), "=r"(r[1]), "=r"(r[2]), "=r"(r[3]) : "r"(addr));
}
__device__ __forceinline__ void ldsm_x4_t(uint32_t* r, uint32_t addr) {
    asm volatile("ldmatrix.sync.aligned.m8n8.x4.trans.shared.b16 {%0,%1,%2,%3}, [%4];"
                 : "=r"(r[0]), "=r"(r[1]), "=r"(r[2]), "=r"(r[3]) : "r"(addr));
}
__device__ __forceinline__ void mma16816(float* c, const uint32_t* a, const uint32_t* b) {
    asm volatile("mma.sync.aligned.m16n8k16.row.col.f32.f16.f16.f32 "
                 "{%0,%1,%2,%3}, {%4,%5,%6,%7}, {%8,%9}, {%0,%1,%2,%3};"
                 : "+f"(c[0]), "+f"(c[1]), "+f"(c[2]), "+f"(c[3])
                 : "r"(a[0]), "r"(a[1]), "r"(a[2]), "r"(a[3]),
                   "r"(b[0]), "r"(b[1]));
}
#define CP16(s, g) asm volatile("cp.async.cg.shared.global [%0], [%1], 16;" :: "r"(s), "l"(g))
#define CP_COMMIT() asm volatile("cp.async.commit_group;" ::: "memory")
#define CP_WAIT(n)  asm volatile("cp.async.wait_group %0;" :: "n"(n) : "memory")

// ---------------------------------------------------------------------------
// Kernel 1: embedding gather/select
// ---------------------------------------------------------------------------
__global__ void gather_kernel(const int* __restrict__ ids,
                              const float* __restrict__ orig_emb,
                              const float* __restrict__ new_emb,
                              float* __restrict__ out) {
    int t = blockIdx.x;
    int id = ids[t];
    const float4* src = (id >= OLDV)
        ? (const float4*)(new_emb + (size_t)(id - OLDV) * EMB_D)
        : (const float4*)(orig_emb + (size_t)id * EMB_D);
    float4* dst = (float4*)(out + (size_t)t * EMB_D);
    int i = threadIdx.x;
    dst[i]       = src[i];
    dst[i + 256] = src[i + 256];
}

// ---------------------------------------------------------------------------
// Kernel 2: h = gelu_exact(feats @ W1 + b1) -> fp16
// ---------------------------------------------------------------------------
__device__ __forceinline__ float gelu_exact(float x) {
    return 0.5f * x * (1.0f + erff(x * 0.70710678118654752440f));
}

__global__ void hidden_kernel(const float* __restrict__ vals,
                              const int* __restrict__ units,
                              const float* __restrict__ unit_emb,
                              const float* __restrict__ W1,
                              const float* __restrict__ b1) {
    int i = blockIdx.y;
    float v = vals[i];
    int u = units[i];
    float e0 = unit_emb[u * 2];
    float e1 = unit_emb[u * 2 + 1];
    int k = (blockIdx.x * blockDim.x + threadIdx.x) * 8;
    __half2 h2[4];
    #pragma unroll
    for (int h = 0; h < 2; h++) {
        float4 w0 = *(const float4*)&W1[k + h * 4];
        float4 w1 = *(const float4*)&W1[KDIM + k + h * 4];
        float4 w2 = *(const float4*)&W1[2 * KDIM + k + h * 4];
        float4 bb = *(const float4*)&b1[k + h * 4];
        float r0 = gelu_exact(fmaf(v, w0.x, fmaf(e0, w1.x, fmaf(e1, w2.x, bb.x))));
        float r1 = gelu_exact(fmaf(v, w0.y, fmaf(e0, w1.y, fmaf(e1, w2.y, bb.y))));
        float r2 = gelu_exact(fmaf(v, w0.z, fmaf(e0, w1.z, fmaf(e1, w2.z, bb.z))));
        float r3 = gelu_exact(fmaf(v, w0.w, fmaf(e0, w1.w, fmaf(e1, w2.w, bb.w))));
        h2[h*2+0] = __floats2half2_rn(r0, r1);
        h2[h*2+1] = __floats2half2_rn(r2, r3);
    }
    *(uint4*)&g_hh[(size_t)i * KDIM + k] = *(uint4*)h2;
}

// ---------------------------------------------------------------------------
// Kernel 3: W2 fp32 -> fp16 (same row-major layout)
// ---------------------------------------------------------------------------
__global__ void w2h_kernel(const float* __restrict__ W2) {
    size_t idx = ((size_t)blockIdx.x * 256 + threadIdx.x) * 8;
    float4 a = *(const float4*)&W2[idx];
    float4 b = *(const float4*)&W2[idx + 4];
    __half2 h2[4];
    h2[0] = __floats2half2_rn(a.x, a.y);
    h2[1] = __floats2half2_rn(a.z, a.w);
    h2[2] = __floats2half2_rn(b.x, b.y);
    h2[3] = __floats2half2_rn(b.z, b.w);
    *(uint4*)&g_w2h[idx] = *(uint4*)h2;
}

// ---------------------------------------------------------------------------
// Kernel 4: fp16 tensor-core GEMM (mma.sync) + scatter-add epilogue
// C[m,n] = sum_k h[m,k] * W2[k,n];  out[pos[m], n] += C + b2[n]
// 128x128x32 tiles, 8 warps (4x2, warp tile 32x64), 4-stage cp.async.
// ---------------------------------------------------------------------------
#define BM 128
#define BN 128
#define BK 32
#define NSTAGE 4
#define STG_B 16384            // per-stage bytes (A 8K + B 8K)
#define SMEM_TOTAL (NSTAGE * STG_B)
#define NIT (KDIM / BK)        // 256

__global__ __launch_bounds__(256, 2)
void gemm_kernel(const float* __restrict__ b2,
                 const int* __restrict__ pos,
                 float* __restrict__ out) {
    extern __shared__ char smem[];
    const uint32_t sbase = s2u(smem);
    const int tid = threadIdx.x;
    const int lane = tid & 31;
    const int wid = tid >> 5;
    const int warp_m = wid >> 1;      // 0..3 (32 rows each)
    const int warp_n = wid & 1;       // 0..1 (64 cols each)
    const int m0 = blockIdx.y * BM;
    const int n0 = blockIdx.x * BN;

    const __half* Ag = g_hh + (size_t)m0 * KDIM;
    const __half* Bg = g_w2h + n0;

    // cp.async mapping: A rows 128 x 4 chunks(16B); B rows 32 x 16 chunks
    const int ar = tid >> 1;                  // 0..127
    const int ac0 = (tid & 1) * 2;            // 0 or 2
    const int bk = tid >> 3;                  // 0..31
    const int bc0 = (tid & 7) * 2;            // 0..14
    const uint32_t a_s0 = sbase + ar * 64 + (((ac0)     ^ ((ar >> 1) & 3)) * 16);
    const uint32_t a_s1 = sbase + ar * 64 + (((ac0 + 1) ^ ((ar >> 1) & 3)) * 16);
    const uint32_t b_s0 = sbase + 8192 + bk * 256 + (((bc0)     ^ (bk & 7)) * 16);
    const uint32_t b_s1 = sbase + 8192 + bk * 256 + (((bc0 + 1) ^ (bk & 7)) * 16);
    const __half* agp = Ag + (size_t)ar * KDIM;

    // prologue: stages 0..2
    #pragma unroll
    for (int s = 0; s < NSTAGE - 1; s++) {
        const uint32_t so = s * STG_B;
        CP16(a_s0 + so, agp + s * BK + ac0 * 8);
        CP16(a_s1 + so, agp + s * BK + (ac0 + 1) * 8);
        const __half* bgp = Bg + (size_t)(s * BK + bk) * NGEMM;
        CP16(b_s0 + so, bgp + bc0 * 8);
        CP16(b_s1 + so, bgp + (bc0 + 1) * 8);
        CP_COMMIT();
    }

    float acc[2][8][4];
    #pragma unroll
    for (int mt = 0; mt < 2; mt++)
        #pragma unroll
        for (int nt = 0; nt < 8; nt++)
            #pragma unroll
            for (int j = 0; j < 4; j++) acc[mt][nt][j] = 0.0f;

    // precomputed fragment smem offsets (relative to stage base)
    uint32_t a_off[2][2], b_off[2][4];
    #pragma unroll
    for (int ks = 0; ks < 2; ks++) {
        #pragma unroll
        for (int mt = 0; mt < 2; mt++) {
            int row = warp_m * 32 + mt * 16 + (lane & 15);
            int ch = ks * 2 + (lane >> 4);
            a_off[ks][mt] = row * 64 + ((ch ^ ((row >> 1) & 3)) * 16);
        }
        #pragma unroll
        for (int np = 0; np < 4; np++) {
            int k = ks * 16 + (lane & 15);
            int ch = warp_n * 8 + np * 2 + (lane >> 4);
            b_off[ks][np] = 8192 + k * 256 + ((ch ^ (k & 7)) * 16);
        }
    }

    #pragma unroll 1
    for (int kt = 0; kt < NIT; kt++) {
        CP_WAIT(NSTAGE - 2);
        __syncthreads();

        // issue loads for tile kt+3 into slot (kt+3)&3
        if (kt + NSTAGE - 1 < NIT) {
            const int s = kt + NSTAGE - 1;
            const uint32_t so = (s & 3) * STG_B;
            CP16(a_s0 + so, agp + s * BK + ac0 * 8);
            CP16(a_s1 + so, agp + s * BK + (ac0 + 1) * 8);
            const __half* bgp = Bg + (size_t)(s * BK + bk) * NGEMM;
            CP16(b_s0 + so, bgp + bc0 * 8);
            CP16(b_s1 + so, bgp + (bc0 + 1) * 8);
        }
        CP_COMMIT();

        const uint32_t st = sbase + (kt & 3) * STG_B;
        #pragma unroll
        for (int ks = 0; ks < 2; ks++) {
            uint32_t a[2][4], b[4][4];
            #pragma unroll
            for (int mt = 0; mt < 2; mt++) ldsm_x4(a[mt], st + a_off[ks][mt]);
            #pragma unroll
            for (int np = 0; np < 4; np++) ldsm_x4_t(b[np], st + b_off[ks][np]);
            #pragma unroll
            for (int mt = 0; mt < 2; mt++) {
                #pragma unroll
                for (int np = 0; np < 4; np++) {
                    mma16816(acc[mt][np * 2],     a[mt], &b[np][0]);
                    mma16816(acc[mt][np * 2 + 1], a[mt], &b[np][2]);
                }
            }
        }
    }

    // epilogue: scatter-add (+ b2) into out rows pos[m]
    #pragma unroll
    for (int mt = 0; mt < 2; mt++) {
        const int rbase = m0 + warp_m * 32 + mt * 16 + (lane >> 2);
        const int p0 = pos[rbase];
        const int p1 = pos[rbase + 8];
        const int cbase = n0 + warp_n * 64 + (lane & 3) * 2;
        float* o0 = out + (size_t)p0 * EMB_D + cbase;
        float* o1 = out + (size_t)p1 * EMB_D + cbase;
        const float* bb = b2 + cbase;
        #pragma unroll
        for (int nt = 0; nt < 8; nt++) {
            float bx = bb[nt * 8], by = bb[nt * 8 + 1];
            float2 v0 = *(float2*)(o0 + nt * 8);
            v0.x += acc[mt][nt][0] + bx;
            v0.y += acc[mt][nt][1] + by;
            *(float2*)(o0 + nt * 8) = v0;
            float2 v1 = *(float2*)(o1 + nt * 8);
            v1.x += acc[mt][nt][2] + bx;
            v1.y += acc[mt][nt][3] + by;
            *(float2*)(o1 + nt * 8) = v1;
        }
    }
}

// ---------------------------------------------------------------------------
extern "C" void kernel_launch(void* const* d_in, const int* in_sizes, int n_in,
                              void* d_out, int out_size) {
    const int*   input_ids  = (const int*)d_in[0];
    const int*   num_pos    = (const int*)d_in[1];
    const float* num_values = (const float*)d_in[2];
    const int*   num_units  = (const int*)d_in[3];
    const float* orig_emb   = (const float*)d_in[4];
    const float* new_emb    = (const float*)d_in[5];
    const float* unit_emb   = (const float*)d_in[6];
    const float* W1         = (const float*)d_in[7];
    const float* b1         = (const float*)d_in[8];
    const float* W2         = (const float*)d_in[9];
    const float* b2         = (const float*)d_in[10];
    float* out = (float*)d_out;

    cudaFuncSetAttribute(gemm_kernel,
                         cudaFuncAttributeMaxDynamicSharedMemorySize, SMEM_TOTAL);

    // 1) gather/select embeddings
    gather_kernel<<<T_TOK, 256>>>(input_ids, orig_emb, new_emb, out);

    // 2) hidden activations -> fp16
    dim3 hgrid(KDIM / (256 * 8), NNUM);
    hidden_kernel<<<hgrid, 256>>>(num_values, num_units, unit_emb, W1, b1);

    // 3) W2 -> fp16
    w2h_kernel<<<(KDIM * NGEMM) / (256 * 8), 256>>>(W2);

    // 4) tensor-core GEMM + scatter-add
    dim3 ggrid(NGEMM / BN, MGEMM / BM);
    gemm_kernel<<<ggrid, 256, SMEM_TOTAL>>>(b2, num_pos, out);
}